// round 8
// baseline (speedup 1.0000x reference)
#include <cuda_runtime.h>
#include <cuda_fp16.h>
#include <cstdint>

#define NMAX   200000
#define GMAX   64
#define MAXDEG 128    // R4-exact: 512B row stride, measured-fast scatter

// ---------------- scratch (device-code references ONLY) ----------------------
__device__ __align__(16) uint4 g_u1h[NMAX];     // 8 x fp16 (6 used): dis*h1
__device__ __align__(16) uint4 g_u2h[NMAX];     // 8 x fp16: dis*relu(layer1)
__device__ int   g_src[(size_t)NMAX * MAXDEG];  // per-dest source buckets
__device__ int   g_deg[NMAX];
__device__ float g_dis[NMAX];
__device__ float g_pool[GMAX * 6];
__device__ float g_cnt[GMAX];

__device__ __forceinline__ void red2(float* p, float a, float b) {
    asm volatile("red.global.add.v2.f32 [%0], {%1,%2};"
                 :: "l"(p), "f"(a), "f"(b) : "memory");
}
__device__ __forceinline__ uint32_t pack2(float a, float b) {
    __half2 h = __floats2half2_rn(a, b);
    return *(uint32_t*)&h;
}
__device__ __forceinline__ __half2 h2(uint32_t w) { return *(__half2*)&w; }
__device__ __forceinline__ uint32_t h2u(__half2 h) { return *(uint32_t*)&h; }
__device__ __forceinline__ __half2 shfl8(__half2 v, int o) {
    return h2(__shfl_xor_sync(0xffffffffu, h2u(v), o, 8));
}

// ---------------- K0: init -----------------------------------------------------
__global__ void kInit(int N) {
    int i = blockIdx.x * blockDim.x + threadIdx.x;
    if (i < N)        g_deg[i]  = 0;
    if (i < GMAX * 6) g_pool[i] = 0.f;
    if (i < GMAX)     g_cnt[i]  = 0.f;
}

// ---------------- K1: bucket scatter (R4-exact form) ----------------------------
__global__ void kScatter(const int* __restrict__ ei, int E) {
    int t = blockIdx.x * blockDim.x + threadIdx.x;
    if (t >= E) return;
    int r = __ldg(ei + t), c = __ldg(ei + E + t);
    int pos = atomicAdd(&g_deg[c], 1);
    if (pos < MAXDEG) g_src[(size_t)c * MAXDEG + pos] = r;
}

// ---------------- K2: u1 = pack_fp16(dis * (x@W1)); dis -------------------------
#define K1_NODES 64
__global__ void __launch_bounds__(64) kH1(const float* __restrict__ x,
                                          const float* __restrict__ W1, int N) {
    __shared__ float sx[K1_NODES * 132];
    __shared__ float sW[768];
    const int tid = threadIdx.x;
    for (int i = tid; i < 768; i += 64) sW[i] = W1[i];

    const int base = blockIdx.x * K1_NODES;
#pragma unroll
    for (int it = 0; it < 32; it++) {
        int f = tid + 64 * it;
        int node = f >> 5, c = f & 31;
        int gn = base + node;
        float4 v = make_float4(0.f, 0.f, 0.f, 0.f);
        if (gn < N) v = *(const float4*)(x + (size_t)gn * 128 + c * 4);
        *(float4*)&sx[node * 132 + c * 4] = v;
    }
    __syncthreads();

    const int gn = base + tid;
    if (gn >= N) return;

    float a0 = 0.f, a1 = 0.f, a2 = 0.f, a3 = 0.f, a4 = 0.f, a5 = 0.f;
#pragma unroll
    for (int c = 0; c < 32; c++) {
        float4 xv = *(const float4*)&sx[tid * 132 + c * 4];
        const float4* wp = (const float4*)&sW[c * 24];   // rows 4c..4c+3 of [128][6]
        float4 w0 = wp[0], w1 = wp[1], w2 = wp[2], w3 = wp[3], w4 = wp[4], w5 = wp[5];
        a0 += xv.x * w0.x + xv.y * w1.z + xv.z * w3.x + xv.w * w4.z;
        a1 += xv.x * w0.y + xv.y * w1.w + xv.z * w3.y + xv.w * w4.w;
        a2 += xv.x * w0.z + xv.y * w2.x + xv.z * w3.z + xv.w * w5.x;
        a3 += xv.x * w0.w + xv.y * w2.y + xv.z * w3.w + xv.w * w5.y;
        a4 += xv.x * w1.x + xv.y * w2.z + xv.z * w4.x + xv.w * w5.z;
        a5 += xv.x * w1.y + xv.y * w2.w + xv.z * w4.y + xv.w * w5.w;
    }
    float d = rsqrtf((float)(g_deg[gn] + 1));   // deg final after kScatter
    g_dis[gn] = d;
    uint4 m;
    m.x = pack2(d * a0, d * a1);
    m.y = pack2(d * a2, d * a3);
    m.z = pack2(d * a4, d * a5);
    m.w = 0u;
    g_u1h[gn] = m;
}

// ---------------- agg core: 8 lanes/node, int4 idx loads, HADD2 accumulation ----
#define AGG_BODY(SRCARR)                                                        \
    int deg = g_deg[n];                                                         \
    int mdeg = (deg < MAXDEG) ? deg : MAXDEG;                                   \
    const int* sp = g_src + (size_t)n * MAXDEG;                                 \
    __half2 A0 = h2(0u), A1 = h2(0u), A2 = h2(0u);                              \
    for (int base = lane * 4; base < mdeg; base += 32) {                        \
        int4 sv = *(const int4*)(sp + base);                                    \
        if (base + 0 < mdeg) { uint4 m = SRCARR[sv.x];                          \
            A0 = __hadd2(A0, h2(m.x)); A1 = __hadd2(A1, h2(m.y));               \
            A2 = __hadd2(A2, h2(m.z)); }                                        \
        if (base + 1 < mdeg) { uint4 m = SRCARR[sv.y];                          \
            A0 = __hadd2(A0, h2(m.x)); A1 = __hadd2(A1, h2(m.y));               \
            A2 = __hadd2(A2, h2(m.z)); }                                        \
        if (base + 2 < mdeg) { uint4 m = SRCARR[sv.z];                          \
            A0 = __hadd2(A0, h2(m.x)); A1 = __hadd2(A1, h2(m.y));               \
            A2 = __hadd2(A2, h2(m.z)); }                                        \
        if (base + 3 < mdeg) { uint4 m = SRCARR[sv.w];                          \
            A0 = __hadd2(A0, h2(m.x)); A1 = __hadd2(A1, h2(m.y));               \
            A2 = __hadd2(A2, h2(m.z)); }                                        \
    }                                                                           \
    _Pragma("unroll")                                                           \
    for (int o = 4; o; o >>= 1) {                                               \
        A0 = __hadd2(A0, shfl8(A0, o));                                         \
        A1 = __hadd2(A1, shfl8(A1, o));                                         \
        A2 = __hadd2(A2, shfl8(A2, o));                                         \
    }

// ---------------- K3: agg layer1 + bias/relu epilogue -> u2 ---------------------
__global__ void kAgg1(const float* __restrict__ b1, int N) {
    __shared__ float sb[6];
    if (threadIdx.x < 6) sb[threadIdx.x] = b1[threadIdx.x];
    __syncthreads();
    int grp  = (blockIdx.x * blockDim.x + threadIdx.x) >> 3;
    int lane = threadIdx.x & 7;
    int n = (grp < N) ? grp : 0;
    AGG_BODY(g_u1h)
    if (grp < N && lane == 0) {
        float d = g_dis[n];
        uint4 ms = g_u1h[n];
        float2 s0 = __half22float2(A0), s1 = __half22float2(A1), s2 = __half22float2(A2);
        float2 u0 = __half22float2(h2(ms.x)), u1 = __half22float2(h2(ms.y)),
               u2 = __half22float2(h2(ms.z));
        float r0 = fmaxf(d * (s0.x + u0.x) + sb[0], 0.f);
        float r1 = fmaxf(d * (s0.y + u0.y) + sb[1], 0.f);
        float r2 = fmaxf(d * (s1.x + u1.x) + sb[2], 0.f);
        float r3 = fmaxf(d * (s1.y + u1.y) + sb[3], 0.f);
        float r4 = fmaxf(d * (s2.x + u2.x) + sb[4], 0.f);
        float r5 = fmaxf(d * (s2.y + u2.y) + sb[5], 0.f);
        uint4 w;
        w.x = pack2(d * r0, d * r1);
        w.y = pack2(d * r2, d * r3);
        w.z = pack2(d * r4, d * r5);
        w.w = 0u;
        g_u2h[n] = w;
    }
}

// ---------------- K4: agg layer2 + fused mean-pool -------------------------------
__global__ void kAgg2(const int* __restrict__ batch, int N) {
    int grp  = (blockIdx.x * blockDim.x + threadIdx.x) >> 3;
    int lane = threadIdx.x & 7;
    int n = (grp < N) ? grp : 0;
    AGG_BODY(g_u2h)
    if (grp < N && lane == 0) {
        float d = g_dis[n];
        uint4 ms = g_u2h[n];
        float2 s0 = __half22float2(A0), s1 = __half22float2(A1), s2 = __half22float2(A2);
        float2 u0 = __half22float2(h2(ms.x)), u1 = __half22float2(h2(ms.y)),
               u2 = __half22float2(h2(ms.z));
        float v0 = d * (s0.x + u0.x), v1 = d * (s0.y + u0.y);
        float v2 = d * (s1.x + u1.x), v3 = d * (s1.y + u1.y);
        float v4 = d * (s2.x + u2.x), v5 = d * (s2.y + u2.y);
        int g = __ldg(batch + n);
        float* dst = g_pool + g * 6;
        red2(dst,     v0, v1);
        red2(dst + 2, v2, v3);
        red2(dst + 4, v4, v5);
        atomicAdd(&g_cnt[g], 1.f);
    }
}

// ---------------- K5: out = log_softmax((pool/cnt)@W2 + b2) ---------------------
__global__ void kOut(const float* __restrict__ W2, const float* __restrict__ b2,
                     float* __restrict__ out, int G) {
    __shared__ float sW[60];
    __shared__ float sb[10];
    if (threadIdx.x < 60) sW[threadIdx.x] = W2[threadIdx.x];
    if (threadIdx.x < 10) sb[threadIdx.x] = b2[threadIdx.x];
    __syncthreads();
    int g = threadIdx.x;
    if (g >= G) return;
    float c = fmaxf(g_cnt[g], 1.f);
    float p[6];
#pragma unroll
    for (int k = 0; k < 6; k++) p[k] = g_pool[g * 6 + k] / c;
    float v[10], m = -1e30f;
#pragma unroll
    for (int j = 0; j < 10; j++) {
        float s = sb[j];
#pragma unroll
        for (int k = 0; k < 6; k++) s += p[k] * sW[k * 10 + j];
        v[j] = s;
        m = fmaxf(m, s);
    }
    float s = 0.f;
#pragma unroll
    for (int j = 0; j < 10; j++) s += expf(v[j] - m);
    float l = m + logf(s);
#pragma unroll
    for (int j = 0; j < 10; j++) out[g * 10 + j] = v[j] - l;
}

// ---------------- launch ----------------------------------------------------------
extern "C" void kernel_launch(void* const* d_in, const int* in_sizes, int n_in,
                              void* d_out, int out_size) {
    const float* x     = (const float*)d_in[0];
    const int*   ei    = (const int*)d_in[1];
    const int*   batch = (const int*)d_in[2];
    const float* W1    = (const float*)d_in[3];
    const float* b1    = (const float*)d_in[4];
    const float* W2    = (const float*)d_in[5];
    const float* b2    = (const float*)d_in[6];

    int N = in_sizes[2];
    int E = in_sizes[1] / 2;
    int G = out_size / 10;
    if (N > NMAX) N = NMAX;

    int nb = (N + 255) / 256;
    int aggBlocks = (N * 8 + 255) / 256;

    kInit   <<<nb, 256>>>(N);
    kScatter<<<(E + 255) / 256, 256>>>(ei, E);
    kH1     <<<(N + K1_NODES - 1) / K1_NODES, 64>>>(x, W1, N);
    kAgg1   <<<aggBlocks, 256>>>(b1, N);        // 4th launch -> ncu capture
    kAgg2   <<<aggBlocks, 256>>>(batch, N);
    kOut    <<<1, 64>>>(W2, b2, (float*)d_out, G);
}

// round 9
// speedup vs baseline: 2.3710x; 2.3710x over previous
#include <cuda_runtime.h>
#include <cuda_fp16.h>
#include <cstdint>

#define NMAX 200000
#define GMAX 64

// ---------------- scratch (device-code references ONLY) ----------------------
__device__ __align__(16) uint4 g_u1h[NMAX];   // 8 x fp16 (6 used): dis*h1
__device__ __align__(16) uint4 g_a1h[NMAX];   // fp16 accumulation, init = self term
__device__ __align__(16) uint4 g_u2h[NMAX];   // 8 x fp16: dis*relu(layer1)
__device__ __align__(16) uint4 g_a2h[NMAX];   // fp16 accumulation, init = self term
__device__ int   g_deg[NMAX];
__device__ float g_dis[NMAX];
__device__ float g_pool[GMAX * 6];
__device__ float g_cnt[GMAX];

// ---------------- helpers ------------------------------------------------------
__device__ __forceinline__ void red2f(float* p, float a, float b) {
    asm volatile("red.global.add.v2.f32 [%0], {%1,%2};"
                 :: "l"(p), "f"(a), "f"(b) : "memory");
}
// single 16B fp16 vector reduction: 8 halves (pads are zero)
__device__ __forceinline__ void red16h(uint4* p, uint4 m) {
    asm volatile("red.global.add.noftz.v4.f16x2 [%0], {%1,%2,%3,%4};"
                 :: "l"(p), "r"(m.x), "r"(m.y), "r"(m.z), "r"(m.w) : "memory");
}
__device__ __forceinline__ uint32_t pack2(float a, float b) {
    __half2 h = __floats2half2_rn(a, b);
    return *(uint32_t*)&h;
}
__device__ __forceinline__ float2 up2(uint32_t w) {
    return __half22float2(*(__half2*)&w);
}

// ---------------- K0: init ------------------------------------------------------
__global__ void kInit(int N) {
    int i = blockIdx.x * blockDim.x + threadIdx.x;
    if (i < N)        g_deg[i]  = 0;
    if (i < GMAX * 6) g_pool[i] = 0.f;
    if (i < GMAX)     g_cnt[i]  = 0.f;
}

// ---------------- K1: degree ----------------------------------------------------
__global__ void kDeg(const int* __restrict__ col, int E) {
    int i = blockIdx.x * blockDim.x + threadIdx.x;
    if (i < E) atomicAdd(&g_deg[col[i]], 1);
}

// ---------------- K2: u1 = pack_fp16(dis*(x@W1)); a1 = u1 (self term) ------------
#define K1_NODES 64
__global__ void __launch_bounds__(64) kH1(const float* __restrict__ x,
                                          const float* __restrict__ W1, int N) {
    __shared__ float sx[K1_NODES * 132];
    __shared__ float sW[768];
    const int tid = threadIdx.x;
    for (int i = tid; i < 768; i += 64) sW[i] = W1[i];

    const int base = blockIdx.x * K1_NODES;
#pragma unroll
    for (int it = 0; it < 32; it++) {
        int f = tid + 64 * it;
        int node = f >> 5, c = f & 31;
        int gn = base + node;
        float4 v = make_float4(0.f, 0.f, 0.f, 0.f);
        if (gn < N) v = *(const float4*)(x + (size_t)gn * 128 + c * 4);
        *(float4*)&sx[node * 132 + c * 4] = v;
    }
    __syncthreads();

    const int gn = base + tid;
    if (gn >= N) return;

    float a0 = 0.f, a1 = 0.f, a2 = 0.f, a3 = 0.f, a4 = 0.f, a5 = 0.f;
#pragma unroll
    for (int c = 0; c < 32; c++) {
        float4 xv = *(const float4*)&sx[tid * 132 + c * 4];
        const float4* wp = (const float4*)&sW[c * 24];   // rows 4c..4c+3 of [128][6]
        float4 w0 = wp[0], w1 = wp[1], w2 = wp[2], w3 = wp[3], w4 = wp[4], w5 = wp[5];
        a0 += xv.x * w0.x + xv.y * w1.z + xv.z * w3.x + xv.w * w4.z;
        a1 += xv.x * w0.y + xv.y * w1.w + xv.z * w3.y + xv.w * w4.w;
        a2 += xv.x * w0.z + xv.y * w2.x + xv.z * w3.z + xv.w * w5.x;
        a3 += xv.x * w0.w + xv.y * w2.y + xv.z * w3.w + xv.w * w5.y;
        a4 += xv.x * w1.x + xv.y * w2.z + xv.z * w4.x + xv.w * w5.z;
        a5 += xv.x * w1.y + xv.y * w2.w + xv.z * w4.y + xv.w * w5.w;
    }
    float d = rsqrtf((float)(g_deg[gn] + 1));   // +1 self-loop
    g_dis[gn] = d;
    uint4 m;
    m.x = pack2(d * a0, d * a1);
    m.y = pack2(d * a2, d * a3);
    m.z = pack2(d * a4, d * a5);
    m.w = 0u;
    g_u1h[gn] = m;       // message
    g_a1h[gn] = m;       // accumulator starts at self term
}

// ---------------- K3/K5: edge pass — 1 gather + 1 vector red per edge ------------
template<int LAYER>
__global__ void kEdge(const int* __restrict__ ei, int E) {
    int t = blockIdx.x * blockDim.x + threadIdx.x;
    if (t >= E) return;
    int r = __ldg(ei + t), c = __ldg(ei + E + t);
    if (LAYER == 1) {
        uint4 m = g_u1h[r];
        red16h(&g_a1h[c], m);
    } else {
        uint4 m = g_u2h[r];
        red16h(&g_a2h[c], m);
    }
}

// ---------------- K4: u2 = pack(dis*relu(dis*a1 + b1)); a2 = u2 -------------------
__global__ void kMid(const float* __restrict__ b1, int N) {
    __shared__ float sb[6];
    if (threadIdx.x < 6) sb[threadIdx.x] = b1[threadIdx.x];
    __syncthreads();
    int i = blockIdx.x * blockDim.x + threadIdx.x;
    if (i >= N) return;
    float d = g_dis[i];
    uint4 a = g_a1h[i];
    float2 s0 = up2(a.x), s1 = up2(a.y), s2 = up2(a.z);
    float r0 = fmaxf(d * s0.x + sb[0], 0.f);
    float r1 = fmaxf(d * s0.y + sb[1], 0.f);
    float r2 = fmaxf(d * s1.x + sb[2], 0.f);
    float r3 = fmaxf(d * s1.y + sb[3], 0.f);
    float r4 = fmaxf(d * s2.x + sb[4], 0.f);
    float r5 = fmaxf(d * s2.y + sb[5], 0.f);
    uint4 w;
    w.x = pack2(d * r0, d * r1);
    w.y = pack2(d * r2, d * r3);
    w.z = pack2(d * r4, d * r5);
    w.w = 0u;
    g_u2h[i] = w;
    g_a2h[i] = w;
}

// ---------------- K6: pool v = dis*a2 (batch sorted, warp-uniform path) ----------
__global__ void kPool(const int* __restrict__ batch, int N) {
    int i = blockIdx.x * blockDim.x + threadIdx.x;
    float v[6];
    float cn = 0.f;
    int g = -1;
    if (i < N) {
        g = batch[i];
        float d = g_dis[i];
        uint4 a = g_a2h[i];
        float2 s0 = up2(a.x), s1 = up2(a.y), s2 = up2(a.z);
        v[0] = d * s0.x; v[1] = d * s0.y;
        v[2] = d * s1.x; v[3] = d * s1.y;
        v[4] = d * s2.x; v[5] = d * s2.y;
        cn = 1.f;
    } else {
#pragma unroll
        for (int j = 0; j < 6; j++) v[j] = 0.f;
    }
    int g0 = __shfl_sync(0xffffffffu, g, 0);
    bool uni = __all_sync(0xffffffffu, g == g0) && (g0 >= 0);
    if (uni) {
#pragma unroll
        for (int j = 0; j < 6; j++) {
#pragma unroll
            for (int o = 16; o; o >>= 1) v[j] += __shfl_xor_sync(0xffffffffu, v[j], o);
        }
#pragma unroll
        for (int o = 16; o; o >>= 1) cn += __shfl_xor_sync(0xffffffffu, cn, o);
        if ((threadIdx.x & 31) == 0) {
            float* dst = g_pool + g0 * 6;
            red2f(dst,     v[0], v[1]);
            red2f(dst + 2, v[2], v[3]);
            red2f(dst + 4, v[4], v[5]);
            atomicAdd(&g_cnt[g0], cn);
        }
    } else if (g >= 0) {
#pragma unroll
        for (int j = 0; j < 6; j++) atomicAdd(&g_pool[g * 6 + j], v[j]);
        atomicAdd(&g_cnt[g], 1.f);
    }
}

// ---------------- K7: out = log_softmax((pool/cnt)@W2 + b2) ----------------------
__global__ void kOut(const float* __restrict__ W2, const float* __restrict__ b2,
                     float* __restrict__ out, int G) {
    __shared__ float sW[60];
    __shared__ float sb[10];
    if (threadIdx.x < 60) sW[threadIdx.x] = W2[threadIdx.x];
    if (threadIdx.x < 10) sb[threadIdx.x] = b2[threadIdx.x];
    __syncthreads();
    int g = threadIdx.x;
    if (g >= G) return;
    float c = fmaxf(g_cnt[g], 1.f);
    float p[6];
#pragma unroll
    for (int k = 0; k < 6; k++) p[k] = g_pool[g * 6 + k] / c;
    float v[10], m = -1e30f;
#pragma unroll
    for (int j = 0; j < 10; j++) {
        float s = sb[j];
#pragma unroll
        for (int k = 0; k < 6; k++) s += p[k] * sW[k * 10 + j];
        v[j] = s;
        m = fmaxf(m, s);
    }
    float s = 0.f;
#pragma unroll
    for (int j = 0; j < 10; j++) s += expf(v[j] - m);
    float l = m + logf(s);
#pragma unroll
    for (int j = 0; j < 10; j++) out[g * 10 + j] = v[j] - l;
}

// ---------------- launch -----------------------------------------------------------
extern "C" void kernel_launch(void* const* d_in, const int* in_sizes, int n_in,
                              void* d_out, int out_size) {
    const float* x     = (const float*)d_in[0];
    const int*   ei    = (const int*)d_in[1];
    const int*   batch = (const int*)d_in[2];
    const float* W1    = (const float*)d_in[3];
    const float* b1    = (const float*)d_in[4];
    const float* W2    = (const float*)d_in[5];
    const float* b2    = (const float*)d_in[6];

    int N = in_sizes[2];
    int E = in_sizes[1] / 2;
    int G = out_size / 10;
    if (N > NMAX) N = NMAX;

    int nb = (N + 255) / 256;
    int eb = (E + 255) / 256;

    kInit    <<<nb, 256>>>(N);
    kDeg     <<<eb, 256>>>(ei + E, E);
    kH1      <<<(N + K1_NODES - 1) / K1_NODES, 64>>>(x, W1, N);
    kEdge<1> <<<eb, 256>>>(ei, E);      // launch idx 3 -> ncu capture
    kMid     <<<nb, 256>>>(b1, N);
    kEdge<2> <<<eb, 256>>>(ei, E);
    kPool    <<<nb, 256>>>(batch, N);
    kOut     <<<1, 64>>>(W2, b2, (float*)d_out, G);
}

// round 10
// speedup vs baseline: 2.5104x; 1.0588x over previous
#include <cuda_runtime.h>
#include <cuda_fp16.h>
#include <cstdint>

#define NMAX 200000
#define GMAX 64

// ---------------- scratch (device-code references ONLY) ----------------------
__device__ __align__(16) uint4 g_h1h[NMAX];   // 8 x fp16 (6 used): UNscaled x@W1
__device__ __align__(16) uint4 g_u1h[NMAX];   // 8 x fp16: dis*h1 (message)
__device__ __align__(16) uint4 g_a1h[NMAX];   // fp16 accumulator, init = self term
__device__ __align__(16) uint4 g_u2h[NMAX];   // 8 x fp16: dis*relu(layer1)
__device__ __align__(16) uint4 g_a2h[NMAX];   // fp16 accumulator, init = self term
__device__ int   g_deg[NMAX];
__device__ float g_dis[NMAX];
__device__ float g_pool[GMAX * 6];
__device__ float g_cnt[GMAX];

// ---------------- helpers ------------------------------------------------------
__device__ __forceinline__ void red2f(float* p, float a, float b) {
    asm volatile("red.global.add.v2.f32 [%0], {%1,%2};"
                 :: "l"(p), "f"(a), "f"(b) : "memory");
}
__device__ __forceinline__ void red16h(uint4* p, uint4 m) {
    asm volatile("red.global.add.noftz.v4.f16x2 [%0], {%1,%2,%3,%4};"
                 :: "l"(p), "r"(m.x), "r"(m.y), "r"(m.z), "r"(m.w) : "memory");
}
__device__ __forceinline__ uint32_t pack2(float a, float b) {
    __half2 h = __floats2half2_rn(a, b);
    return *(uint32_t*)&h;
}
__device__ __forceinline__ float2 up2(uint32_t w) {
    return __half22float2(*(__half2*)&w);
}

// ---------------- K0: init ------------------------------------------------------
__global__ void kInit(int N) {
    int i = blockIdx.x * blockDim.x + threadIdx.x;
    if (i < N)        g_deg[i]  = 0;
    if (i < GMAX * 6) g_pool[i] = 0.f;
    if (i < GMAX)     g_cnt[i]  = 0.f;
}

// ---------------- K1: fused deg-count + H1 matmul (interleaved roles) -----------
// Deg blocks: fire-and-forget RED on L2-resident g_deg (no return, no dep store).
// H1 blocks: 32-node tile, 128 threads, ~20KB SMEM -> ~11 blocks/SM.
#define H1_NODES 32
__global__ void __launch_bounds__(128) kFused(const float* __restrict__ x,
                                              const int* __restrict__ col,
                                              const float* __restrict__ W1,
                                              int N, int E, int HB, int R) {
    __shared__ float sx[H1_NODES * 132];
    __shared__ float sW[768];
    int bid = blockIdx.x;
    int q = bid / R, r = bid % R;
    bool isH1 = (r == R - 1) && (q < HB);

    if (!isH1) {
        int h1Before = q + ((r == R - 1) ? 1 : 0);
        if (h1Before > HB) h1Before = HB;
        int eb = bid - h1Before;             // deg block index
        int e = eb * 128 + threadIdx.x;
        if (e < E) atomicAdd(&g_deg[__ldg(col + e)], 1);
        return;
    }

    // ---- H1 tile q: 32 nodes ----
    const int tid = threadIdx.x;
    for (int i = tid; i < 768; i += 128) sW[i] = W1[i];
    const int base = q * H1_NODES;
#pragma unroll
    for (int it = 0; it < 8; it++) {
        int f = tid + 128 * it;              // float4 id (1024 total)
        int node = f >> 5, c = f & 31;
        int gn = base + node;
        float4 v = make_float4(0.f, 0.f, 0.f, 0.f);
        if (gn < N) v = *(const float4*)(x + (size_t)gn * 128 + c * 4);
        *(float4*)&sx[node * 132 + c * 4] = v;
    }
    __syncthreads();

    int node = tid >> 2, sub = tid & 3;      // 4 threads per node
    int gn = base + node;
    float a0 = 0.f, a1 = 0.f, a2 = 0.f, a3 = 0.f, a4 = 0.f, a5 = 0.f;
#pragma unroll
    for (int c = sub; c < 32; c += 4) {
        float4 xv = *(const float4*)&sx[node * 132 + c * 4];
        const float4* wp = (const float4*)&sW[c * 24];   // rows 4c..4c+3 of [128][6]
        float4 w0 = wp[0], w1 = wp[1], w2 = wp[2], w3 = wp[3], w4 = wp[4], w5 = wp[5];
        a0 += xv.x * w0.x + xv.y * w1.z + xv.z * w3.x + xv.w * w4.z;
        a1 += xv.x * w0.y + xv.y * w1.w + xv.z * w3.y + xv.w * w4.w;
        a2 += xv.x * w0.z + xv.y * w2.x + xv.z * w3.z + xv.w * w5.x;
        a3 += xv.x * w0.w + xv.y * w2.y + xv.z * w3.w + xv.w * w5.y;
        a4 += xv.x * w1.x + xv.y * w2.z + xv.z * w4.x + xv.w * w5.z;
        a5 += xv.x * w1.y + xv.y * w2.w + xv.z * w4.y + xv.w * w5.w;
    }
#pragma unroll
    for (int o = 2; o; o >>= 1) {
        a0 += __shfl_xor_sync(0xffffffffu, a0, o, 4);
        a1 += __shfl_xor_sync(0xffffffffu, a1, o, 4);
        a2 += __shfl_xor_sync(0xffffffffu, a2, o, 4);
        a3 += __shfl_xor_sync(0xffffffffu, a3, o, 4);
        a4 += __shfl_xor_sync(0xffffffffu, a4, o, 4);
        a5 += __shfl_xor_sync(0xffffffffu, a5, o, 4);
    }
    if (sub == 0 && gn < N) {
        uint4 m;
        m.x = pack2(a0, a1);
        m.y = pack2(a2, a3);
        m.z = pack2(a4, a5);
        m.w = 0u;
        g_h1h[gn] = m;                       // unscaled; dis applied in kU1
    }
}

// ---------------- K2: u1 = dis * h1 (fp16 in/out); a1 = u1; dis ------------------
__global__ void kU1(int N) {
    int i = blockIdx.x * blockDim.x + threadIdx.x;
    if (i >= N) return;
    float d = rsqrtf((float)(g_deg[i] + 1));   // +1 self-loop
    g_dis[i] = d;
    uint4 h = g_h1h[i];
    float2 s0 = up2(h.x), s1 = up2(h.y), s2 = up2(h.z);
    uint4 m;
    m.x = pack2(d * s0.x, d * s0.y);
    m.y = pack2(d * s1.x, d * s1.y);
    m.z = pack2(d * s2.x, d * s2.y);
    m.w = 0u;
    g_u1h[i] = m;
    g_a1h[i] = m;
}

// ---------------- K3/K5: edge pass — 1 gather + 1 vector red per edge ------------
template<int LAYER>
__global__ void kEdge(const int* __restrict__ ei, int E) {
    int t = blockIdx.x * blockDim.x + threadIdx.x;
    if (t >= E) return;
    int r = __ldg(ei + t), c = __ldg(ei + E + t);
    if (LAYER == 1) {
        uint4 m = g_u1h[r];
        red16h(&g_a1h[c], m);
    } else {
        uint4 m = g_u2h[r];
        red16h(&g_a2h[c], m);
    }
}

// ---------------- K4: u2 = pack(dis*relu(dis*a1 + b1)); a2 = u2 -------------------
__global__ void kMid(const float* __restrict__ b1, int N) {
    __shared__ float sb[6];
    if (threadIdx.x < 6) sb[threadIdx.x] = b1[threadIdx.x];
    __syncthreads();
    int i = blockIdx.x * blockDim.x + threadIdx.x;
    if (i >= N) return;
    float d = g_dis[i];
    uint4 a = g_a1h[i];
    float2 s0 = up2(a.x), s1 = up2(a.y), s2 = up2(a.z);
    float r0 = fmaxf(d * s0.x + sb[0], 0.f);
    float r1 = fmaxf(d * s0.y + sb[1], 0.f);
    float r2 = fmaxf(d * s1.x + sb[2], 0.f);
    float r3 = fmaxf(d * s1.y + sb[3], 0.f);
    float r4 = fmaxf(d * s2.x + sb[4], 0.f);
    float r5 = fmaxf(d * s2.y + sb[5], 0.f);
    uint4 w;
    w.x = pack2(d * r0, d * r1);
    w.y = pack2(d * r2, d * r3);
    w.z = pack2(d * r4, d * r5);
    w.w = 0u;
    g_u2h[i] = w;
    g_a2h[i] = w;
}

// ---------------- K6: pool v = dis*a2 (batch sorted, warp-uniform path) ----------
__global__ void kPool(const int* __restrict__ batch, int N) {
    int i = blockIdx.x * blockDim.x + threadIdx.x;
    float v[6];
    float cn = 0.f;
    int g = -1;
    if (i < N) {
        g = batch[i];
        float d = g_dis[i];
        uint4 a = g_a2h[i];
        float2 s0 = up2(a.x), s1 = up2(a.y), s2 = up2(a.z);
        v[0] = d * s0.x; v[1] = d * s0.y;
        v[2] = d * s1.x; v[3] = d * s1.y;
        v[4] = d * s2.x; v[5] = d * s2.y;
        cn = 1.f;
    } else {
#pragma unroll
        for (int j = 0; j < 6; j++) v[j] = 0.f;
    }
    int g0 = __shfl_sync(0xffffffffu, g, 0);
    bool uni = __all_sync(0xffffffffu, g == g0) && (g0 >= 0);
    if (uni) {
#pragma unroll
        for (int j = 0; j < 6; j++) {
#pragma unroll
            for (int o = 16; o; o >>= 1) v[j] += __shfl_xor_sync(0xffffffffu, v[j], o);
        }
#pragma unroll
        for (int o = 16; o; o >>= 1) cn += __shfl_xor_sync(0xffffffffu, cn, o);
        if ((threadIdx.x & 31) == 0) {
            float* dst = g_pool + g0 * 6;
            red2f(dst,     v[0], v[1]);
            red2f(dst + 2, v[2], v[3]);
            red2f(dst + 4, v[4], v[5]);
            atomicAdd(&g_cnt[g0], cn);
        }
    } else if (g >= 0) {
#pragma unroll
        for (int j = 0; j < 6; j++) atomicAdd(&g_pool[g * 6 + j], v[j]);
        atomicAdd(&g_cnt[g], 1.f);
    }
}

// ---------------- K7: out = log_softmax((pool/cnt)@W2 + b2) ----------------------
__global__ void kOut(const float* __restrict__ W2, const float* __restrict__ b2,
                     float* __restrict__ out, int G) {
    __shared__ float sW[60];
    __shared__ float sb[10];
    if (threadIdx.x < 60) sW[threadIdx.x] = W2[threadIdx.x];
    if (threadIdx.x < 10) sb[threadIdx.x] = b2[threadIdx.x];
    __syncthreads();
    int g = threadIdx.x;
    if (g >= G) return;
    float c = fmaxf(g_cnt[g], 1.f);
    float p[6];
#pragma unroll
    for (int k = 0; k < 6; k++) p[k] = g_pool[g * 6 + k] / c;
    float v[10], m = -1e30f;
#pragma unroll
    for (int j = 0; j < 10; j++) {
        float s = sb[j];
#pragma unroll
        for (int k = 0; k < 6; k++) s += p[k] * sW[k * 10 + j];
        v[j] = s;
        m = fmaxf(m, s);
    }
    float s = 0.f;
#pragma unroll
    for (int j = 0; j < 10; j++) s += expf(v[j] - m);
    float l = m + logf(s);
#pragma unroll
    for (int j = 0; j < 10; j++) out[g * 10 + j] = v[j] - l;
}

// ---------------- launch -----------------------------------------------------------
extern "C" void kernel_launch(void* const* d_in, const int* in_sizes, int n_in,
                              void* d_out, int out_size) {
    const float* x     = (const float*)d_in[0];
    const int*   ei    = (const int*)d_in[1];
    const int*   batch = (const int*)d_in[2];
    const float* W1    = (const float*)d_in[3];
    const float* b1    = (const float*)d_in[4];
    const float* W2    = (const float*)d_in[5];
    const float* b2    = (const float*)d_in[6];

    int N = in_sizes[2];
    int E = in_sizes[1] / 2;
    int G = out_size / 10;
    if (N > NMAX) N = NMAX;

    int nb = (N + 255) / 256;
    int eb = (E + 255) / 256;

    int DB = (E + 127) / 128;                // deg blocks (128 threads each)
    int HB = (N + H1_NODES - 1) / H1_NODES;  // H1 tiles
    int grid = DB + HB;
    int R = grid / HB;                       // floor; all H1 slots < grid

    kInit    <<<nb, 256>>>(N);
    kFused   <<<grid, 128>>>(x, ei + E, W1, N, E, HB, R);
    kU1      <<<nb, 256>>>(N);
    kEdge<1> <<<eb, 256>>>(ei, E);           // 4th launch -> ncu capture
    kMid     <<<nb, 256>>>(b1, N);
    kEdge<2> <<<eb, 256>>>(ei, E);
    kPool    <<<nb, 256>>>(batch, N);
    kOut     <<<1, 64>>>(W2, b2, (float*)d_out, G);
}